// round 13
// baseline (speedup 1.0000x reference)
#include <cuda_runtime.h>
#include <math.h>

#define NUM_PINS 4194304
#define NUM_NETS 524288
#define TB 128
#define SPAN 1024            // pins owned per block
#define EXT  1088            // staged window = SPAN + 64 margin (max net ~35)
#define NCAP 1024            // hard bound: at most SPAN net-starts per block
#define CHUNK (SPAN / TB)    // 8 positions per thread
#define GRID (NUM_PINS / SPAN)
#define GL 0.36067376022224085f   // 0.25 * log2(e)

__device__ float    g_acc;   // zero at load; reset by last block each launch
__device__ unsigned g_done;

// ---- f32x2 packed helpers (sm_100a) ----
typedef unsigned long long u64;
__device__ __forceinline__ u64 pk2(float lo, float hi) {
    u64 r; asm("mov.b64 %0, {%1,%2};" : "=l"(r) : "f"(lo), "f"(hi)); return r;
}
__device__ __forceinline__ void up2(u64 v, float& lo, float& hi) {
    asm("mov.b64 {%0,%1}, %2;" : "=f"(lo), "=f"(hi) : "l"(v));
}
#define FMA2(d,a,b,c) asm("fma.rn.f32x2 %0, %1, %2, %3;" : "=l"(d) : "l"(a), "l"(b), "l"(c))
#define ADD2(d,a,b)   asm("add.rn.f32x2 %0, %1, %2;"     : "=l"(d) : "l"(a), "l"(b))
__device__ __forceinline__ float ex2a(float a) {
    float r; asm("ex2.approx.f32 %0, %1;" : "=f"(r) : "f"(a)); return r;
}
__device__ __forceinline__ unsigned smem_u32(const void* p) {
    return (unsigned)__cvta_generic_to_shared(p);
}
#define CPA16(dst, src) \
    asm volatile("cp.async.cg.shared.global [%0], [%1], 16;" :: "r"(dst), "l"(src) : "memory")

// ONE kernel: block owns a 1024-pin window of the SORTED pin2net_map.
// Finds net starts in-window, sorts nets by size (descending), computes the
// per-net WA wirelength + direction penalty, reduces globally via last-block.
__global__ void __launch_bounds__(TB, 8) fused_kernel(
    const float* __restrict__ X,
    const float* __restrict__ Y,
    const float* __restrict__ DX,
    const float* __restrict__ DY,
    const float* __restrict__ W,
    const int*   __restrict__ seg,
    float* __restrict__ out)
{
    __shared__ __align__(16) float SX[EXT], SY[EXT], SDX[EXT], SDY[EXT];
    __shared__ __align__(16) int   SSEG[EXT];
    __shared__ unsigned short s_pos[NCAP];   // net starts (window-relative), ascending
    __shared__ unsigned short s_sst[NCAP];   // sorted (descending size) starts
    __shared__ unsigned short s_sen[NCAP];   // sorted ends (0xFFFF -> s_tail_en)
    __shared__ int s_hist[32], s_offs[32];
    __shared__ int s_wsum[4];
    __shared__ int s_tail_en;
    __shared__ float swarp[4];

    const int tid  = threadIdx.x;
    const int p0   = blockIdx.x * SPAN;
    const int glim = NUM_PINS - p0;               // >= SPAN
    const int limW = glim < EXT ? glim : EXT;     // staged element count

    if (tid < 32) s_hist[tid] = 0;

    // group A: seg window
    for (int i = tid * 4; i < limW; i += TB * 4)
        CPA16(smem_u32(&SSEG[i]), seg + p0 + i);
    asm volatile("cp.async.commit_group;" ::: "memory");
    // group B: four data streams
    for (int i = tid * 4; i < limW; i += TB * 4) {
        CPA16(smem_u32(&SX[i]),  X  + p0 + i);
        CPA16(smem_u32(&SY[i]),  Y  + p0 + i);
        CPA16(smem_u32(&SDX[i]), DX + p0 + i);
        CPA16(smem_u32(&SDY[i]), DY + p0 + i);
    }
    asm volatile("cp.async.commit_group;" ::: "memory");

    // neighbor value before the window (L1 broadcast; overlaps the waits)
    const int prv0 = (p0 > 0) ? __ldg(seg + p0 - 1) : -1;

    asm volatile("cp.async.wait_group 1;" ::: "memory");   // seg ready
    __syncthreads();

    // ---- pass A: count boundaries in my contiguous chunk ----
    const int lane = tid & 31, wid = tid >> 5;
    int prev = (tid == 0) ? prv0 : SSEG[tid * CHUNK - 1];
    int lc = 0;
    #pragma unroll
    for (int c = 0; c < CHUNK; c++) {
        int cur = SSEG[tid * CHUNK + c];
        lc += (cur != prev);
        prev = cur;
    }
    // block exclusive scan of lc
    int incl = lc;
    #pragma unroll
    for (int off = 1; off < 32; off <<= 1) {
        int u = __shfl_up_sync(0xffffffffu, incl, off);
        if (lane >= off) incl += u;
    }
    if (lane == 31) s_wsum[wid] = incl;
    __syncthreads();
    int wbase = 0;
    #pragma unroll
    for (int w2 = 0; w2 < 4; w2++) wbase += (w2 < wid) ? s_wsum[w2] : 0;
    const int cnt = s_wsum[0] + s_wsum[1] + s_wsum[2] + s_wsum[3];
    // ---- pass B: write start positions (sorted ascending by construction) ----
    prev = (tid == 0) ? prv0 : SSEG[tid * CHUNK - 1];
    int r = wbase + incl - lc;
    #pragma unroll
    for (int c = 0; c < CHUNK; c++) {
        int cur = SSEG[tid * CHUNK + c];
        if (cur != prev) s_pos[r++] = (unsigned short)(tid * CHUNK + c);
        prev = cur;
    }
    __syncthreads();

    // ---- loop1: sizes -> histogram; remember (rank,bin) per handled net ----
    unsigned short pkv[NCAP / TB];
    int c1 = 0;
    for (int k = tid; k < cnt; k += TB, c1++) {
        int st = s_pos[k];
        int en;
        if (k + 1 < cnt) en = s_pos[k + 1];
        else {
            // last net: scan staged seg past SPAN, then global (rare) for its end
            int v = SSEG[st];
            int i = SPAN;
            while (i < limW && SSEG[i] == v) i++;
            if (i == limW && p0 + limW < NUM_PINS) {
                int gi = p0 + i;
                while (gi < NUM_PINS && __ldg(seg + gi) == v) gi++;
                i = gi - p0;
            }
            en = i;
            s_tail_en = en;
        }
        int sz   = en - st;
        int bin  = sz < 31 ? sz : 31;
        int rank = atomicAdd(&s_hist[bin], 1);
        pkv[c1]  = (unsigned short)((rank << 5) | bin);
    }
    __syncthreads();
    if (tid < 32) {
        int c = s_hist[tid];
        int v = c;
        #pragma unroll
        for (int off = 1; off < 32; off <<= 1) {
            int u = __shfl_up_sync(0xffffffffu, v, off);
            if (tid >= off) v += u;
        }
        s_offs[tid] = v - c;
    }
    __syncthreads();
    // ---- loop2: scatter DESCENDING by size (overflow sweeps get tiny nets) ----
    c1 = 0;
    for (int k = tid; k < cnt; k += TB, c1++) {
        int bin  = pkv[c1] & 31;
        int rank = pkv[c1] >> 5;
        int pos  = cnt - 1 - (s_offs[bin] + rank);
        int st   = s_pos[k];
        int en   = (k + 1 < cnt) ? (int)s_pos[k + 1] : s_tail_en;
        s_sst[pos] = (unsigned short)st;
        s_sen[pos] = (en < 65535) ? (unsigned short)en : (unsigned short)65535;
    }

    asm volatile("cp.async.wait_group 0;" ::: "memory");   // data ready
    __syncthreads();

    // ---- process nets ----
    float contrib = 0.0f;
    for (int k = tid; k < cnt; k += TB) {
        const int st = s_sst[k];
        int en = s_sen[k];
        if (en == 65535) en = s_tail_en;
        const int cn = en - st;
        if (cn <= 1) continue;   // single-pin nets contribute exactly 0

        const float w = __ldg(W + SSEG[st]);

        const int js  = st;
        const int je  = en;
        const int jeH = je < limW ? je : limW;
        const int jcS = js > limW ? js : limW;

        // Pass 1: max/min/sum
        float xmax = -3.402823466e38f, xmin = 3.402823466e38f;
        float ymax = -3.402823466e38f, ymin = 3.402823466e38f;
        u64 sum2 = pk2(0.0f, 0.0f);
        #pragma unroll 2
        for (int j = js; j < jeH; j++) {
            float px = SX[j], py = SY[j];
            xmax = fmaxf(xmax, px); xmin = fminf(xmin, px);
            ymax = fmaxf(ymax, py); ymin = fminf(ymin, py);
            u64 t; asm("mov.b64 %0, {%1,%2};" : "=l"(t) : "f"(px), "f"(py));
            ADD2(sum2, sum2, t);
        }
        for (int j = jcS; j < je; j++) {          // normally zero trips
            float px = __ldg(X + p0 + j), py = __ldg(Y + p0 + j);
            xmax = fmaxf(xmax, px); xmin = fminf(xmin, px);
            ymax = fmaxf(ymax, py); ymin = fminf(ymin, py);
            u64 t = pk2(px, py);
            ADD2(sum2, sum2, t);
        }
        float sumx, sumy; up2(sum2, sumx, sumy);

        const float rc = __fdividef(1.0f, (float)cn);
        const float cx = sumx * rc;
        const float cy = sumy * rc;

        // Pass 2: packed WA sums + direction penalty
        const u64 g2    = pk2(GL, GL);
        const u64 ng2   = pk2(-GL, -GL);
        const u64 cmaxg = pk2(-xmax * GL, -ymax * GL);
        const u64 cming = pk2(xmin * GL, ymin * GL);
        const u64 c2    = pk2(cx, cy);
        const u64 none2 = pk2(-1.0f, -1.0f);
        const u64 onec  = pk2(1.0f, 1.0f);
        u64 se2 = pk2(0.f, 0.f), sve2 = pk2(0.f, 0.f);
        u64 sm2 = pk2(0.f, 0.f), svm2 = pk2(0.f, 0.f);
        float pen = 0.f;

        #pragma unroll 2
        for (int j = js; j < jeH; j++) {
            float px = SX[j],  py  = SY[j];
            float ddx = SDX[j], ddy = SDY[j];
            u64 t; asm("mov.b64 %0, {%1,%2};" : "=l"(t) : "f"(px), "f"(py));

            u64 argp, argm;
            FMA2(argp, t, g2,  cmaxg);
            FMA2(argm, t, ng2, cming);
            float apx, apy, amx, amy;
            up2(argp, apx, apy);
            up2(argm, amx, amy);
            u64 ep2 = pk2(ex2a(apx), ex2a(apy));
            u64 em2 = pk2(ex2a(amx), ex2a(amy));

            FMA2(se2,  ep2, onec, se2);
            FMA2(sve2, t,   ep2,  sve2);
            FMA2(sm2,  em2, onec, sm2);
            FMA2(svm2, t,   em2,  svm2);

            u64 dd2;
            FMA2(dd2, t, none2, c2);
            float dxp, dyp;
            up2(dd2, dxp, dyp);
            float r2  = fmaxf(fmaf(dxp, dxp, dyp * dyp), 1e-16f);
            float dot = fmaf(dxp, ddx, dyp * ddy);
            float cc  = dot * rsqrtf(r2);
            pen += fmaxf(0.5f - cc, 0.0f);
        }
        for (int j = jcS; j < je; j++) {          // normally zero trips
            float px = __ldg(X + p0 + j),  py  = __ldg(Y + p0 + j);
            float ddx = __ldg(DX + p0 + j), ddy = __ldg(DY + p0 + j);
            u64 t = pk2(px, py);

            u64 argp, argm;
            FMA2(argp, t, g2,  cmaxg);
            FMA2(argm, t, ng2, cming);
            float apx, apy, amx, amy;
            up2(argp, apx, apy);
            up2(argm, amx, amy);
            u64 ep2 = pk2(ex2a(apx), ex2a(apy));
            u64 em2 = pk2(ex2a(amx), ex2a(amy));

            FMA2(se2,  ep2, onec, se2);
            FMA2(sve2, t,   ep2,  sve2);
            FMA2(sm2,  em2, onec, sm2);
            FMA2(svm2, t,   em2,  svm2);

            u64 dd2;
            FMA2(dd2, t, none2, c2);
            float dxp, dyp;
            up2(dd2, dxp, dyp);
            float r2  = fmaxf(fmaf(dxp, dxp, dyp * dyp), 1e-16f);
            float dot = fmaf(dxp, ddx, dyp * ddy);
            float cc  = dot * rsqrtf(r2);
            pen += fmaxf(0.5f - cc, 0.0f);
        }

        float sex, sey, svex, svey, smx, smy, svmx, svmy;
        up2(se2, sex, sey);   up2(sve2, svex, svey);
        up2(sm2, smx, smy);   up2(svm2, svmx, svmy);

        // se/sm >= 1 always (max/min pin contributes exp(0)=1): no eps guards.
        float wax = __fdividef(svex, sex) - __fdividef(svmx, smx);
        float way = __fdividef(svey, sey) - __fdividef(svmy, smy);
        float wl  = fmaxf(wax + way, 0.0f);        // ALPHA == 1.0
        contrib += w * (1.0f + pen * rc) * wl;     // net_mask == 1
    }

    // ---- block reduction, then global last-block reduction ----
    float v = contrib;
    #pragma unroll
    for (int off = 16; off > 0; off >>= 1)
        v += __shfl_down_sync(0xffffffffu, v, off);
    if (lane == 0) swarp[wid] = v;
    __syncthreads();
    if (tid == 0) {
        v = swarp[0] + swarp[1] + swarp[2] + swarp[3];
        atomicAdd(&g_acc, v);
        __threadfence();
        unsigned t = atomicAdd(&g_done, 1u);
        if (t == GRID - 1) {
            out[0] = atomicExch(&g_acc, 0.0f);  // read final sum, reset for next replay
            g_done = 0;
            __threadfence();
        }
    }
}

extern "C" void kernel_launch(void* const* d_in, const int* in_sizes, int n_in,
                              void* d_out, int out_size)
{
    const float* pos  = (const float*)d_in[0];   // 2*P floats: x then y
    const float* dirx = (const float*)d_in[1];
    const float* diry = (const float*)d_in[2];
    const float* w    = (const float*)d_in[3];
    const int*   seg  = (const int*)d_in[4];
    float* out = (float*)d_out;

    fused_kernel<<<GRID, TB>>>(pos, pos + NUM_PINS, dirx, diry, w, seg, out);
}